// round 4
// baseline (speedup 1.0000x reference)
#include <cuda_runtime.h>
#include <cuda_bf16.h>

// CRF loss: forward algorithm (scaled linear-domain scan) + gold score, fused.
// Layout: 1 warp per batch element, lane = tag (T == 32).
// Inputs (metadata order): efeats f32 (B,L,T), mask f32 (B,L), tgt i32 (B,L),
// transitions f32 (T,T). Output: 1 float (loss).

#define BB 256
#define LL 2048
#define TT 32
#define START_IDX 0
#define STOP_IDX 1

__device__ float g_partial[BB];

__global__ void __launch_bounds__(32) crf_fwd_kernel(
    const float* __restrict__ efeats,
    const float* __restrict__ mask,
    const int*   __restrict__ tgt,
    const float* __restrict__ transitions)
{
    __shared__ float tr[TT * TT];
    const int lane = threadIdx.x;
    const int b = blockIdx.x;

    // transitions -> smem (for gold gather + terminal row)
    #pragma unroll
    for (int i = lane; i < TT * TT; i += 32) tr[i] = transitions[i];
    __syncwarp();

    // E row for my 'next' tag: E[next=lane][prev=k] = exp(trans[next, prev])
    float Er[TT];
    #pragma unroll
    for (int k = 0; k < TT; k++) Er[k] = __expf(tr[lane * TT + k]);

    const float* fb = efeats + (size_t)b * LL * TT;
    const float* mb = mask   + (size_t)b * LL;
    const int*   tb = tgt    + (size_t)b * LL;

    // Scaled-domain state: fv[tag] = log(q[tag]) + off_e * ln2
    // init: fv = -10000 except fv[START]=0  ->  q = (1,0,...,0), off = 0
    float q = (lane == START_IDX) ? 1.0f : 0.0f;
    long long off_e = 0;

    // gold-score state
    int   prev   = START_IDX;
    float gtrans = 0.0f;
    float gemit  = 0.0f;
    int   cnt    = 0;

    for (int l0 = 0; l0 < LL; l0 += 8) {
        // prefetch 8 steps of data (feats per-lane coalesced; mask/tgt uniform vec loads)
        float f[8];
        #pragma unroll
        for (int i = 0; i < 8; i++) f[i] = fb[(l0 + i) * TT + lane];
        float4 m01 = *(const float4*)(mb + l0);
        float4 m23 = *(const float4*)(mb + l0 + 4);
        int4   t01 = *(const int4*)(tb + l0);
        int4   t23 = *(const int4*)(tb + l0 + 4);
        float mk[8] = {m01.x, m01.y, m01.z, m01.w, m23.x, m23.y, m23.z, m23.w};
        int   tg[8] = {t01.x, t01.y, t01.z, t01.w, t23.x, t23.y, t23.z, t23.w};

        #pragma unroll
        for (int i = 0; i < 8; i++) {
            float ef = __expf(f[i]);   // off the critical chain (depends only on prefetched feat)

            // y[next=lane] = sum_prev q[prev] * E[lane][prev]  (4 independent FMA chains)
            float y0 = 0.f, y1 = 0.f, y2 = 0.f, y3 = 0.f;
            #pragma unroll
            for (int k = 0; k < TT; k += 4) {
                y0 = fmaf(__shfl_sync(0xffffffffu, q, k + 0), Er[k + 0], y0);
                y1 = fmaf(__shfl_sync(0xffffffffu, q, k + 1), Er[k + 1], y1);
                y2 = fmaf(__shfl_sync(0xffffffffu, q, k + 2), Er[k + 2], y2);
                y3 = fmaf(__shfl_sync(0xffffffffu, q, k + 3), Er[k + 3], y3);
            }
            float qn = ef * ((y0 + y1) + (y2 + y3));

            bool on  = mk[i] > 0.0f;         // uniform across warp
            int  tag = tg[i];
            if (on) {
                q = qn;
                cnt++;
                gtrans += tr[tag * TT + prev];        // uniform LDS
                if (lane == tag) gemit += f[i];       // emit term lives in this lane
            }
            prev = tag;

            // rescale every 4 steps by exact power of 2 (exponent of q[0]);
            // scale and integer offset are exact inverses -> no drift.
            if ((i & 3) == 3) {
                float q0 = __shfl_sync(0xffffffffu, q, 0);
                int e = (__float_as_int(q0) >> 23) & 0xff;   // biased exponent
                q *= __int_as_float((unsigned)(254 - e) << 23);  // * 2^(127 - e)
                off_e += (long long)(e - 127);
            }
        }
    }

    // terminal: forward = off + log( sum_next q[next] * exp(trans[STOP, next]) )
    float t = q * __expf(tr[STOP_IDX * TT + lane]);
    #pragma unroll
    for (int o = 16; o; o >>= 1) t += __shfl_xor_sync(0xffffffffu, t, o);
    #pragma unroll
    for (int o = 16; o; o >>= 1) gemit += __shfl_xor_sync(0xffffffffu, gemit, o);

    if (lane == 0) {
        double fwd = (double)off_e * 0.6931471805599453 + (double)logf(t);
        int last = (cnt == 0) ? START_IDX : tb[cnt - 1];
        double gold = (double)gtrans + (double)gemit + (double)tr[STOP_IDX * TT + last];
        g_partial[b] = (float)(fwd - gold);
    }
}

__global__ void crf_reduce_kernel(float* __restrict__ out)
{
    const int tid = threadIdx.x;   // 256 threads
    __shared__ float s[8];
    float v = g_partial[tid];
    #pragma unroll
    for (int o = 16; o; o >>= 1) v += __shfl_xor_sync(0xffffffffu, v, o);
    if ((tid & 31) == 0) s[tid >> 5] = v;
    __syncthreads();
    if (tid < 32) {
        float x = (tid < 8) ? s[tid] : 0.0f;
        #pragma unroll
        for (int o = 4; o; o >>= 1) x += __shfl_xor_sync(0xffffffffu, x, o);
        if (tid == 0) *out = x / (float)BB;
    }
}

extern "C" void kernel_launch(void* const* d_in, const int* in_sizes, int n_in,
                              void* d_out, int out_size)
{
    const float* efeats      = (const float*)d_in[0];
    const float* mask        = (const float*)d_in[1];
    const int*   tgt         = (const int*)  d_in[2];
    const float* transitions = (const float*)d_in[3];
    float* out = (float*)d_out;

    crf_fwd_kernel<<<BB, 32>>>(efeats, mask, tgt, transitions);
    crf_reduce_kernel<<<1, BB>>>(out);
}

// round 5
// speedup vs baseline: 1.5359x; 1.5359x over previous
#include <cuda_runtime.h>
#include <cuda_bf16.h>

// CRF loss: scaled linear-domain forward scan + gold score, fused.
// Layout: 1 warp (= 1 block, so BAR.SYNC floor is 3 cyc) per batch element.
// Each lane holds the FULL q vector (32 floats) in registers plus its own
// packed exp-transition row; the per-step matvec is 16 packed fma.rn.f32x2
// with zero shuffles. q_new is broadcast via a ping-pong smem buffer:
// 1 STS + __syncthreads() + 8 broadcast LDS.128 per step.

#define BB 256
#define LL 2048
#define TT 32
#define START_IDX 0
#define STOP_IDX 1

typedef unsigned long long u64;

__device__ float g_partial[BB];

__device__ __forceinline__ u64 ffma2(u64 a, u64 b, u64 c) {
    u64 d; asm("fma.rn.f32x2 %0, %1, %2, %3;" : "=l"(d) : "l"(a), "l"(b), "l"(c)); return d;
}
__device__ __forceinline__ u64 fadd2(u64 a, u64 b) {
    u64 d; asm("add.rn.f32x2 %0, %1, %2;" : "=l"(d) : "l"(a), "l"(b)); return d;
}
__device__ __forceinline__ u64 fmul2(u64 a, u64 b) {
    u64 d; asm("mul.rn.f32x2 %0, %1, %2;" : "=l"(d) : "l"(a), "l"(b)); return d;
}
__device__ __forceinline__ u64 pack2(float lo, float hi) {
    return ((u64)__float_as_uint(hi) << 32) | (u64)__float_as_uint(lo);
}
__device__ __forceinline__ float lo2(u64 v) { return __uint_as_float((unsigned)v); }
__device__ __forceinline__ float hi2(u64 v) { return __uint_as_float((unsigned)(v >> 32)); }

__global__ void __launch_bounds__(32) crf_fwd_kernel(
    const float* __restrict__ efeats,
    const float* __restrict__ mask,
    const int*   __restrict__ tgt,
    const float* __restrict__ transitions)
{
    __shared__ __align__(16) float sq[2][TT];   // ping-pong broadcast buffers
    __shared__ float tr[TT * TT];
    const int lane = threadIdx.x;
    const int b = blockIdx.x;

    #pragma unroll
    for (int i = lane; i < TT * TT; i += 32) tr[i] = transitions[i];
    __syncthreads();

    // Packed E row for my 'next' tag: Erp[j] = (exp(tr[lane][2j]), exp(tr[lane][2j+1]))
    u64 Erp[16];
    #pragma unroll
    for (int j = 0; j < 16; j++)
        Erp[j] = pack2(__expf(tr[lane * TT + 2 * j]), __expf(tr[lane * TT + 2 * j + 1]));

    // Full q vector per lane (packed): init q = unit vector at START_IDX
    u64 qp[16];
    #pragma unroll
    for (int j = 0; j < 16; j++) qp[j] = 0ull;
    qp[START_IDX / 2] = (START_IDX & 1) ? pack2(0.0f, 1.0f) : pack2(1.0f, 0.0f);

    const float* fb = efeats + (size_t)b * LL * TT;
    const float* mb = mask   + (size_t)b * LL;
    const int*   tb = tgt    + (size_t)b * LL;

    long long off_e = 0;           // exact power-of-2 scaling offset (exponent units)
    int   buf    = 0;
    int   prev   = START_IDX;
    float gtrans = 0.0f;
    float gemit  = 0.0f;
    int   cnt    = 0;

    for (int l0 = 0; l0 < LL; l0 += 8) {
        // prefetch 8 steps (feats coalesced per-lane; mask/tgt uniform vec loads)
        float f[8], ef[8];
        #pragma unroll
        for (int i = 0; i < 8; i++) f[i] = fb[(l0 + i) * TT + lane];
        #pragma unroll
        for (int i = 0; i < 8; i++) ef[i] = __expf(f[i]);   // off the critical chain
        float4 m01 = *(const float4*)(mb + l0);
        float4 m23 = *(const float4*)(mb + l0 + 4);
        int4   t01 = *(const int4*)(tb + l0);
        int4   t23 = *(const int4*)(tb + l0 + 4);
        float mk[8] = {m01.x, m01.y, m01.z, m01.w, m23.x, m23.y, m23.z, m23.w};
        int   tg[8] = {t01.x, t01.y, t01.z, t01.w, t23.x, t23.y, t23.z, t23.w};

        #pragma unroll
        for (int i = 0; i < 8; i++) {
            const bool on  = mk[i] > 0.0f;   // warp-uniform
            const int  tag = tg[i];
            if (on) {
                // y[lane] = sum_k q[k] * Er_lane[k] : 16 packed FMAs, 4 chains, all registers
                u64 a0 = 0ull, a1 = 0ull, a2 = 0ull, a3 = 0ull;
                #pragma unroll
                for (int j = 0; j < 16; j += 4) {
                    a0 = ffma2(qp[j + 0], Erp[j + 0], a0);
                    a1 = ffma2(qp[j + 1], Erp[j + 1], a1);
                    a2 = ffma2(qp[j + 2], Erp[j + 2], a2);
                    a3 = ffma2(qp[j + 3], Erp[j + 3], a3);
                }
                u64 s = fadd2(fadd2(a0, a1), fadd2(a2, a3));
                float qnew = ef[i] * (lo2(s) + hi2(s));

                // broadcast: 1 STS + 3-cycle BAR + 8 broadcast LDS.128
                sq[buf][lane] = qnew;
                __syncthreads();
                const ulonglong2* p = (const ulonglong2*)sq[buf];
                #pragma unroll
                for (int j = 0; j < 8; j++) {
                    ulonglong2 v = p[j];
                    qp[2 * j]     = v.x;
                    qp[2 * j + 1] = v.y;
                }
                buf ^= 1;

                // gold-path terms
                cnt++;
                gtrans += tr[tag * TT + prev];       // uniform broadcast LDS
                if (lane == tag) gemit += f[i];

                // exact power-of-2 rescale every 4 active steps (no shuffle:
                // every lane holds q[0] locally; identical across lanes)
                if ((cnt & 3) == 0) {
                    int e = (int)(((unsigned)qp[0] >> 23) & 0xff);
                    float sc = __int_as_float((unsigned)(254 - e) << 23);  // 2^(127-e)
                    u64 sc2 = pack2(sc, sc);
                    #pragma unroll
                    for (int j = 0; j < 16; j++) qp[j] = fmul2(qp[j], sc2);
                    off_e += (long long)(e - 127);
                }
            }
            prev = tag;
        }
    }

    // terminal logsumexp — every lane holds the full q vector, compute redundantly
    float t = 0.0f;
    #pragma unroll
    for (int j = 0; j < 16; j++) {
        t += lo2(qp[j]) * __expf(tr[STOP_IDX * TT + 2 * j]);
        t += hi2(qp[j]) * __expf(tr[STOP_IDX * TT + 2 * j + 1]);
    }

    // only the emit term is lane-distributed — one final warp reduction
    #pragma unroll
    for (int o = 16; o; o >>= 1) gemit += __shfl_xor_sync(0xffffffffu, gemit, o);

    if (lane == 0) {
        double fwd = (double)off_e * 0.6931471805599453 + (double)logf(t);
        int last = (cnt == 0) ? START_IDX : tb[cnt - 1];
        double gold = (double)gtrans + (double)gemit + (double)tr[STOP_IDX * TT + last];
        g_partial[b] = (float)(fwd - gold);
    }
}

__global__ void crf_reduce_kernel(float* __restrict__ out)
{
    const int tid = threadIdx.x;   // 256 threads
    __shared__ float s[8];
    float v = g_partial[tid];
    #pragma unroll
    for (int o = 16; o; o >>= 1) v += __shfl_xor_sync(0xffffffffu, v, o);
    if ((tid & 31) == 0) s[tid >> 5] = v;
    __syncthreads();
    if (tid < 32) {
        float x = (tid < 8) ? s[tid] : 0.0f;
        #pragma unroll
        for (int o = 4; o; o >>= 1) x += __shfl_xor_sync(0xffffffffu, x, o);
        if (tid == 0) *out = x / (float)BB;
    }
}

extern "C" void kernel_launch(void* const* d_in, const int* in_sizes, int n_in,
                              void* d_out, int out_size)
{
    const float* efeats      = (const float*)d_in[0];
    const float* mask        = (const float*)d_in[1];
    const int*   tgt         = (const int*)  d_in[2];
    const float* transitions = (const float*)d_in[3];
    float* out = (float*)d_out;

    crf_fwd_kernel<<<BB, 32>>>(efeats, mask, tgt, transitions);
    crf_reduce_kernel<<<1, BB>>>(out);
}